// round 14
// baseline (speedup 1.0000x reference)
#include <cuda_runtime.h>
#include <math.h>
#include <stdint.h>

// Problem constants
#define B   64
#define TP  400
#define TQ  60
#define DP  512
#define DQ  512
#define NH  256
#define G4  1024   // 4*NH

// ---------------------------------------------------------------------------
// Device scratch (static globals: allocation-free, zero-initialized at load)
// ---------------------------------------------------------------------------
__device__ float g_h[2 * 2 * B * NH];      // [buf][dir][b][h]  double-buffered hidden
__device__ float g_c[2 * B * NH];          // [dir][b][h]       cell state
__device__ float g_ctx[2 * B * DQ];        // [dir][b][d]       attention context
__device__ float g_Pproj[B * TP * NH];     // p @ Wp
__device__ float g_qWq[B * TQ * NH];       // q @ Wq + b_att
__device__ float g_PihF[B * TP * G4];      // p @ Wih_f[0:512] + b_f
__device__ float g_PihB[B * TP * G4];      // p @ Wih_b[0:512] + b_b

// ---------------------------------------------------------------------------
// Fast, accurate-enough activations (abs err ~1e-6; clamped against __fdividef
// large-denominator pathology)
// ---------------------------------------------------------------------------
__device__ __forceinline__ float ftanh(float x) {
    x = fminf(fmaxf(x, -15.f), 15.f);
    float e = __expf(2.f * x);
    return 1.f - __fdividef(2.f, e + 1.f);
}
__device__ __forceinline__ float fsigmoid(float x) {
    x = fminf(fmaxf(x, -30.f), 30.f);
    return __fdividef(1.f, 1.f + __expf(-x));
}

// ---------------------------------------------------------------------------
// Tiled SGEMM: C[M,N] = A[M,K] @ W[K,N] (+bias). A row-major lda=K,
// W row-major ldw, C row-major ldc=N. M%128==0, N%128==0, K%8==0 (guaranteed).
// BM=BN=128, BK=8, 256 threads, 8x8 per-thread microtile.
// ---------------------------------------------------------------------------
__global__ __launch_bounds__(256) void sgemm128(
    const float* __restrict__ A, const float* __restrict__ W,
    const float* __restrict__ bias, float* __restrict__ C,
    int M, int N, int K, int ldw)
{
    __shared__ float As[8][128];
    __shared__ float Bs[8][128];

    const int tid = threadIdx.x;
    const int m0 = blockIdx.y * 128;
    const int n0 = blockIdx.x * 128;
    const int tx = tid & 15;
    const int ty = tid >> 4;

    const int arow = tid >> 1;
    const int acol = (tid & 1) * 4;
    const int brow = tid >> 5;
    const int bcol = (tid & 31) * 4;

    const float* Aptr = A + (size_t)(m0 + arow) * K + acol;
    const float* Wptr = W + (size_t)brow * ldw + n0 + bcol;

    float acc[8][8];
#pragma unroll
    for (int i = 0; i < 8; i++)
#pragma unroll
        for (int j = 0; j < 8; j++) acc[i][j] = 0.f;

    for (int kt = 0; kt < K; kt += 8) {
        float4 av = *(const float4*)(Aptr + kt);
        float4 bv = *(const float4*)(Wptr + (size_t)kt * ldw);
        As[acol + 0][arow] = av.x;
        As[acol + 1][arow] = av.y;
        As[acol + 2][arow] = av.z;
        As[acol + 3][arow] = av.w;
        *(float4*)&Bs[brow][bcol] = bv;
        __syncthreads();

#pragma unroll
        for (int kk = 0; kk < 8; kk++) {
            float am[8], bn[8];
            *(float4*)(am)     = *(const float4*)&As[kk][ty * 8];
            *(float4*)(am + 4) = *(const float4*)&As[kk][ty * 8 + 4];
            *(float4*)(bn)     = *(const float4*)&Bs[kk][tx * 8];
            *(float4*)(bn + 4) = *(const float4*)&Bs[kk][tx * 8 + 4];
#pragma unroll
            for (int i = 0; i < 8; i++)
#pragma unroll
                for (int j = 0; j < 8; j++)
                    acc[i][j] = fmaf(am[i], bn[j], acc[i][j]);
        }
        __syncthreads();
    }

#pragma unroll
    for (int i = 0; i < 8; i++) {
        int row = m0 + ty * 8 + i;
        float* Crow = C + (size_t)row * N + n0 + tx * 8;
#pragma unroll
        for (int j = 0; j < 8; j += 4) {
            float4 v;
            v.x = acc[i][j + 0];
            v.y = acc[i][j + 1];
            v.z = acc[i][j + 2];
            v.w = acc[i][j + 3];
            if (bias) {
                int nb = n0 + tx * 8 + j;
                v.x += bias[nb + 0];
                v.y += bias[nb + 1];
                v.z += bias[nb + 2];
                v.w += bias[nb + 3];
            }
            *(float4*)(Crow + j) = v;
        }
    }
}

// ---------------------------------------------------------------------------
// Init: zero hidden buffer 0 and cell state (every launch, for determinism)
// ---------------------------------------------------------------------------
__global__ void init_states() {
    int i = blockIdx.x * 256 + threadIdx.x;   // 32768 threads
    g_h[i] = 0.f;   // first 2*B*NH = 32768 floats of g_h == buffer 0
    g_c[i] = 0.f;
}

// ---------------------------------------------------------------------------
// Per-step attention kernel: one CTA per (dir, b). 256 threads.
// v = Pproj[b,tsel,:] + h @ Wr; s_j = sum_h tanh(qWq+v)*w_score + mask bias;
// softmax over TQ; ctx = alpha @ q.
// ---------------------------------------------------------------------------
__global__ __launch_bounds__(256) void attn_step_kernel(
    const float* __restrict__ input_q, const float* __restrict__ mask_q,
    const float* __restrict__ Wr, const float* __restrict__ w_score, int t)
{
    __shared__ float sh_h[NH];
    __shared__ float sh_v[NH];
    __shared__ float sh_ws[NH];
    __shared__ float sh_alpha[TQ];

    const int bid = blockIdx.x;
    const int dir = bid >> 6;
    const int b   = bid & 63;
    const int tsel = dir ? (TP - 1 - t) : t;
    const int tid = threadIdx.x;
    const int bufR = t & 1;

    sh_h[tid]  = g_h[bufR * (2 * B * NH) + dir * (B * NH) + b * NH + tid];
    sh_ws[tid] = w_score[tid];
    __syncthreads();

    // v[tid] = Pproj + h @ Wr[:, tid]
    float acc = g_Pproj[(b * TP + tsel) * NH + tid];
#pragma unroll 8
    for (int k = 0; k < NH; k++)
        acc = fmaf(sh_h[k], __ldg(&Wr[k * NH + tid]), acc);
    sh_v[tid] = acc;
    __syncthreads();

    // scores: 8 warps stride over j
    const int warp = tid >> 5, lane = tid & 31;
    const float* qwq_b = g_qWq + b * TQ * NH;
    for (int j = warp; j < TQ; j += 8) {
        const float* row = qwq_b + j * NH;
        float p = 0.f;
#pragma unroll
        for (int hh = 0; hh < NH / 32; hh++) {
            int h = hh * 32 + lane;
            p += ftanh(row[h] + sh_v[h]) * sh_ws[h];
        }
#pragma unroll
        for (int off = 16; off; off >>= 1)
            p += __shfl_xor_sync(0xffffffffu, p, off);
        if (lane == 0)
            sh_alpha[j] = p + (mask_q[b * TQ + j] - 1.f) * 1e9f;
    }
    __syncthreads();

    // softmax over TQ=60 by warp 0
    if (tid < 32) {
        float s0 = (tid < TQ)      ? sh_alpha[tid]      : -1e30f;
        float s1 = (tid + 32 < TQ) ? sh_alpha[tid + 32] : -1e30f;
        float mx = fmaxf(s0, s1);
#pragma unroll
        for (int off = 16; off; off >>= 1)
            mx = fmaxf(mx, __shfl_xor_sync(0xffffffffu, mx, off));
        float e0 = (tid < TQ)      ? __expf(s0 - mx) : 0.f;
        float e1 = (tid + 32 < TQ) ? __expf(s1 - mx) : 0.f;
        float sm = e0 + e1;
#pragma unroll
        for (int off = 16; off; off >>= 1)
            sm += __shfl_xor_sync(0xffffffffu, sm, off);
        float inv = __fdividef(1.f, sm);
        if (tid < TQ)      sh_alpha[tid]      = e0 * inv;
        if (tid + 32 < TQ) sh_alpha[tid + 32] = e1 * inv;
    }
    __syncthreads();

    // ctx[d] = sum_j alpha_j * q[b,j,d]
    const float* qb = input_q + (size_t)b * TQ * DQ;
    for (int d = tid; d < DQ; d += 256) {
        float c = 0.f;
#pragma unroll 10
        for (int j = 0; j < TQ; j++)
            c = fmaf(sh_alpha[j], __ldg(&qb[j * DQ + d]), c);
        g_ctx[dir * (B * DQ) + b * DQ + d] = c;
    }
}

// ---------------------------------------------------------------------------
// Per-step gates kernel: one CTA per (dir, 4-hidden-column slice). 256 threads.
// gates = Pih[b,tsel,:] + ctx @ Wih[512:1024,:] + h @ Whh; LSTM update + store.
// Weight columns are read from L2 exactly once per step per element.
// ---------------------------------------------------------------------------
__global__ __launch_bounds__(256) void gates_step_kernel(
    const float* __restrict__ Wih_f, const float* __restrict__ Whh_f,
    const float* __restrict__ Wih_b, const float* __restrict__ Whh_b,
    const float* __restrict__ mask_p, float* __restrict__ out, int t)
{
    __shared__ float zs[64][65];   // padded to kill bank conflicts
    __shared__ float ws[64][16];   // [kk][idx*4 + gate]

    const int bid   = blockIdx.x;
    const int dir   = bid >> 6;
    const int slice = bid & 63;
    const int hbase = slice * 4;
    const int tid = threadIdx.x;
    const int b   = tid & 63;
    const int idx = tid >> 6;           // 0..3
    const int bufR = t & 1;
    const int bufW = bufR ^ 1;

    const float* Wih = dir ? Wih_b : Wih_f;
    const float* Whh = dir ? Whh_b : Whh_f;
    const float* ctx_base = g_ctx + dir * (B * DQ);
    const float* h_base   = g_h + bufR * (2 * B * NH) + dir * (B * NH);

    float ai = 0.f, af = 0.f, ag = 0.f, ao = 0.f;

    for (int kc = 0; kc < DQ + NH; kc += 64) {
        // load z chunk [64 b][64 k]
        const float* src;
        int ld;
        if (kc < DQ) { src = ctx_base + kc; ld = DQ; }
        else         { src = h_base + (kc - DQ); ld = NH; }
#pragma unroll
        for (int i = tid; i < 64 * 64; i += 256) {
            int bb = i >> 6, kk = i & 63;
            zs[bb][kk] = src[bb * ld + kk];
        }
        // load weight chunk [64 k][16 cols]
        const float* wsrc = (kc < DQ) ? (Wih + (size_t)(DQ + kc) * G4)
                                      : (Whh + (size_t)(kc - DQ) * G4);
#pragma unroll
        for (int i = tid; i < 64 * 16; i += 256) {
            int kk = i >> 4, c = i & 15;
            int col = (c & 3) * NH + hbase + (c >> 2);
            ws[kk][c] = wsrc[(size_t)kk * G4 + col];
        }
        __syncthreads();

#pragma unroll
        for (int kk = 0; kk < 64; kk++) {
            float a = zs[b][kk];
            float4 w = *(const float4*)&ws[kk][idx * 4];
            ai = fmaf(a, w.x, ai);
            af = fmaf(a, w.y, af);
            ag = fmaf(a, w.z, ag);
            ao = fmaf(a, w.w, ao);
        }
        __syncthreads();
    }

    // LSTM update
    const int tsel = dir ? (TP - 1 - t) : t;
    const int hcol = hbase + idx;
    const float* Pih = (dir ? g_PihB : g_PihF) + ((size_t)b * TP + tsel) * G4;

    float gi = ai + Pih[hcol];
    float gf = af + Pih[NH + hcol];
    float gg = ag + Pih[2 * NH + hcol];
    float go = ao + Pih[3 * NH + hcol];

    float i_ = fsigmoid(gi);
    float f_ = fsigmoid(gf);
    float o_ = fsigmoid(go);
    float g_ = ftanh(gg);

    int sidx = dir * (B * NH) + b * NH + hcol;
    float c_old = g_c[sidx];
    float h_old = g_h[bufR * (2 * B * NH) + sidx];
    float nc = f_ * c_old + i_ * g_;
    float nh = o_ * ftanh(nc);

    float m = mask_p[b * TP + tsel];
    float hn = m * nh + (1.f - m) * h_old;
    float cn = m * nc + (1.f - m) * c_old;

    g_h[bufW * (2 * B * NH) + sidx] = hn;
    g_c[sidx] = cn;
    out[((size_t)b * TP + tsel) * (2 * NH) + dir * NH + hcol] = hn * m;
}

// ---------------------------------------------------------------------------
// Epilogue: concat_last = [h_f_final, h_b_final] (buffer (TP&1)==0)
// ---------------------------------------------------------------------------
__global__ void finalize_kernel(float* __restrict__ out) {
    int i = blockIdx.x * 256 + threadIdx.x;   // 2*B*NH = 32768
    int dir = i / (B * NH);
    int b   = (i / NH) & 63;
    int h   = i & (NH - 1);
    const size_t OFF_LAST = (size_t)B * TP * (2 * NH);
    out[OFF_LAST + b * (2 * NH) + dir * NH + h] =
        g_h[/*buf0*/ dir * (B * NH) + b * NH + h];
}

// ---------------------------------------------------------------------------
// Launch
// ---------------------------------------------------------------------------
extern "C" void kernel_launch(void* const* d_in, const int* in_sizes, int n_in,
                              void* d_out, int out_size)
{
    const float* input_p = (const float*)d_in[0];
    const float* mask_p  = (const float*)d_in[1];
    const float* input_q = (const float*)d_in[2];
    const float* mask_q  = (const float*)d_in[3];
    const float* Wp      = (const float*)d_in[4];
    const float* Wq      = (const float*)d_in[5];
    const float* Wr      = (const float*)d_in[6];
    const float* b_att   = (const float*)d_in[7];
    const float* w_score = (const float*)d_in[8];
    const float* Wih_f   = (const float*)d_in[9];
    const float* Whh_f   = (const float*)d_in[10];
    const float* b_f     = (const float*)d_in[11];
    const float* Wih_b   = (const float*)d_in[12];
    const float* Whh_b   = (const float*)d_in[13];
    const float* b_b     = (const float*)d_in[14];
    float* out = (float*)d_out;

    float *pproj, *qwq, *pihf, *pihb;
    cudaGetSymbolAddress((void**)&pproj, g_Pproj);
    cudaGetSymbolAddress((void**)&qwq,   g_qWq);
    cudaGetSymbolAddress((void**)&pihf,  g_PihF);
    cudaGetSymbolAddress((void**)&pihb,  g_PihB);

    // reset states (required: kernel is replayed)
    init_states<<<128, 256>>>();

    // time-parallel precompute GEMMs
    sgemm128<<<dim3(2, 30), 256>>>(input_q, Wq, b_att, qwq, B * TQ, NH, DQ, NH);
    sgemm128<<<dim3(2, 200), 256>>>(input_p, Wp, nullptr, pproj, B * TP, NH, DP, NH);
    sgemm128<<<dim3(8, 200), 256>>>(input_p, Wih_f, b_f, pihf, B * TP, G4, DP, G4);
    sgemm128<<<dim3(8, 200), 256>>>(input_p, Wih_b, b_b, pihb, B * TP, G4, DP, G4);

    // sequential recurrence (fwd + bwd run concurrently inside each kernel)
    for (int t = 0; t < TP; t++) {
        attn_step_kernel<<<128, 256>>>(input_q, mask_q, Wr, w_score, t);
        gates_step_kernel<<<128, 256>>>(Wih_f, Whh_f, Wih_b, Whh_b,
                                        mask_p, out, t);
    }

    finalize_kernel<<<128, 256>>>(out);
}

// round 15
// speedup vs baseline: 1.0872x; 1.0872x over previous
#include <cuda_runtime.h>
#include <math.h>
#include <stdint.h>

// Problem constants
#define B   64
#define TP  400
#define TQ  60
#define DP  512
#define DQ  512
#define NH  256
#define G4  1024   // 4*NH

// ---------------------------------------------------------------------------
// Device scratch (static globals: allocation-free, zero-initialized at load)
// ---------------------------------------------------------------------------
__device__ float g_h[2 * 2 * B * NH];      // [buf][dir][b][h]  double-buffered hidden
__device__ float g_c[2 * B * NH];          // [dir][b][h]       cell state
__device__ float g_ctx[2 * B * DQ];        // [dir][b][d]       attention context
__device__ float g_Pproj[B * TP * NH];     // p @ Wp
__device__ float g_qWq[B * TQ * NH];       // q @ Wq + b_att
__device__ float g_PihF[B * TP * G4];      // p @ Wih_f[0:512] + b_f
__device__ float g_PihB[B * TP * G4];      // p @ Wih_b[0:512] + b_b

// ---------------------------------------------------------------------------
// Fast, accurate-enough activations (abs err ~1e-6; clamped against __fdividef
// large-denominator pathology)
// ---------------------------------------------------------------------------
__device__ __forceinline__ float ftanh(float x) {
    x = fminf(fmaxf(x, -15.f), 15.f);
    float e = __expf(2.f * x);
    return 1.f - __fdividef(2.f, e + 1.f);
}
__device__ __forceinline__ float fsigmoid(float x) {
    x = fminf(fmaxf(x, -30.f), 30.f);
    return __fdividef(1.f, 1.f + __expf(-x));
}

// ---------------------------------------------------------------------------
// Tiled SGEMM: C[M,N] = A[M,K] @ W[K,N] (+bias). A row-major lda=K,
// W row-major ldw, C row-major ldc=N. M%128==0, N%128==0, K%8==0 (guaranteed).
// BM=BN=128, BK=8, 256 threads, 8x8 per-thread microtile.
// ---------------------------------------------------------------------------
__global__ __launch_bounds__(256) void sgemm128(
    const float* __restrict__ A, const float* __restrict__ W,
    const float* __restrict__ bias, float* __restrict__ C,
    int M, int N, int K, int ldw)
{
    __shared__ float As[8][128];
    __shared__ float Bs[8][128];

    const int tid = threadIdx.x;
    const int m0 = blockIdx.y * 128;
    const int n0 = blockIdx.x * 128;
    const int tx = tid & 15;
    const int ty = tid >> 4;

    const int arow = tid >> 1;
    const int acol = (tid & 1) * 4;
    const int brow = tid >> 5;
    const int bcol = (tid & 31) * 4;

    const float* Aptr = A + (size_t)(m0 + arow) * K + acol;
    const float* Wptr = W + (size_t)brow * ldw + n0 + bcol;

    float acc[8][8];
#pragma unroll
    for (int i = 0; i < 8; i++)
#pragma unroll
        for (int j = 0; j < 8; j++) acc[i][j] = 0.f;

    for (int kt = 0; kt < K; kt += 8) {
        float4 av = *(const float4*)(Aptr + kt);
        float4 bv = *(const float4*)(Wptr + (size_t)kt * ldw);
        As[acol + 0][arow] = av.x;
        As[acol + 1][arow] = av.y;
        As[acol + 2][arow] = av.z;
        As[acol + 3][arow] = av.w;
        *(float4*)&Bs[brow][bcol] = bv;
        __syncthreads();

#pragma unroll
        for (int kk = 0; kk < 8; kk++) {
            float am[8], bn[8];
            *(float4*)(am)     = *(const float4*)&As[kk][ty * 8];
            *(float4*)(am + 4) = *(const float4*)&As[kk][ty * 8 + 4];
            *(float4*)(bn)     = *(const float4*)&Bs[kk][tx * 8];
            *(float4*)(bn + 4) = *(const float4*)&Bs[kk][tx * 8 + 4];
#pragma unroll
            for (int i = 0; i < 8; i++)
#pragma unroll
                for (int j = 0; j < 8; j++)
                    acc[i][j] = fmaf(am[i], bn[j], acc[i][j]);
        }
        __syncthreads();
    }

#pragma unroll
    for (int i = 0; i < 8; i++) {
        int row = m0 + ty * 8 + i;
        float* Crow = C + (size_t)row * N + n0 + tx * 8;
#pragma unroll
        for (int j = 0; j < 8; j += 4) {
            float4 v;
            v.x = acc[i][j + 0];
            v.y = acc[i][j + 1];
            v.z = acc[i][j + 2];
            v.w = acc[i][j + 3];
            if (bias) {
                int nb = n0 + tx * 8 + j;
                v.x += bias[nb + 0];
                v.y += bias[nb + 1];
                v.z += bias[nb + 2];
                v.w += bias[nb + 3];
            }
            *(float4*)(Crow + j) = v;
        }
    }
}

// ---------------------------------------------------------------------------
// Init: zero hidden buffer 0 and cell state (every launch, for determinism)
// ---------------------------------------------------------------------------
__global__ void init_states() {
    int i = blockIdx.x * 256 + threadIdx.x;   // 32768 threads
    g_h[i] = 0.f;   // first 2*B*NH = 32768 floats of g_h == buffer 0
    g_c[i] = 0.f;
}

// ---------------------------------------------------------------------------
// Per-step attention kernel: one CTA per (dir, b). 256 threads.
// v = Pproj[b,tsel,:] + h @ Wr; s_j = sum_h tanh(qWq+v)*w_score + mask bias;
// softmax over TQ; ctx = alpha @ q.
// ---------------------------------------------------------------------------
__global__ __launch_bounds__(256) void attn_step_kernel(
    const float* __restrict__ input_q, const float* __restrict__ mask_q,
    const float* __restrict__ Wr, const float* __restrict__ w_score, int t)
{
    __shared__ float sh_h[NH];
    __shared__ float sh_v[NH];
    __shared__ float sh_ws[NH];
    __shared__ float sh_alpha[TQ];

    const int bid = blockIdx.x;
    const int dir = bid >> 6;
    const int b   = bid & 63;
    const int tsel = dir ? (TP - 1 - t) : t;
    const int tid = threadIdx.x;
    const int bufR = t & 1;

    sh_h[tid]  = g_h[bufR * (2 * B * NH) + dir * (B * NH) + b * NH + tid];
    sh_ws[tid] = w_score[tid];
    __syncthreads();

    // v[tid] = Pproj + h @ Wr[:, tid]
    float acc = g_Pproj[(b * TP + tsel) * NH + tid];
#pragma unroll 8
    for (int k = 0; k < NH; k++)
        acc = fmaf(sh_h[k], __ldg(&Wr[k * NH + tid]), acc);
    sh_v[tid] = acc;
    __syncthreads();

    // scores: 8 warps stride over j
    const int warp = tid >> 5, lane = tid & 31;
    const float* qwq_b = g_qWq + b * TQ * NH;
    for (int j = warp; j < TQ; j += 8) {
        const float* row = qwq_b + j * NH;
        float p = 0.f;
#pragma unroll
        for (int hh = 0; hh < NH / 32; hh++) {
            int h = hh * 32 + lane;
            p += ftanh(row[h] + sh_v[h]) * sh_ws[h];
        }
#pragma unroll
        for (int off = 16; off; off >>= 1)
            p += __shfl_xor_sync(0xffffffffu, p, off);
        if (lane == 0)
            sh_alpha[j] = p + (mask_q[b * TQ + j] - 1.f) * 1e9f;
    }
    __syncthreads();

    // softmax over TQ=60 by warp 0
    if (tid < 32) {
        float s0 = (tid < TQ)      ? sh_alpha[tid]      : -1e30f;
        float s1 = (tid + 32 < TQ) ? sh_alpha[tid + 32] : -1e30f;
        float mx = fmaxf(s0, s1);
#pragma unroll
        for (int off = 16; off; off >>= 1)
            mx = fmaxf(mx, __shfl_xor_sync(0xffffffffu, mx, off));
        float e0 = (tid < TQ)      ? __expf(s0 - mx) : 0.f;
        float e1 = (tid + 32 < TQ) ? __expf(s1 - mx) : 0.f;
        float sm = e0 + e1;
#pragma unroll
        for (int off = 16; off; off >>= 1)
            sm += __shfl_xor_sync(0xffffffffu, sm, off);
        float inv = __fdividef(1.f, sm);
        if (tid < TQ)      sh_alpha[tid]      = e0 * inv;
        if (tid + 32 < TQ) sh_alpha[tid + 32] = e1 * inv;
    }
    __syncthreads();

    // ctx[d] = sum_j alpha_j * q[b,j,d]
    const float* qb = input_q + (size_t)b * TQ * DQ;
    for (int d = tid; d < DQ; d += 256) {
        float c = 0.f;
#pragma unroll 10
        for (int j = 0; j < TQ; j++)
            c = fmaf(sh_alpha[j], __ldg(&qb[j * DQ + d]), c);
        g_ctx[dir * (B * DQ) + b * DQ + d] = c;
    }
}

// ---------------------------------------------------------------------------
// Per-step gates kernel: one CTA per (dir, 4-hidden-column slice). 256 threads.
// gates = Pih[b,tsel,:] + ctx @ Wih[512:1024,:] + h @ Whh; LSTM update + store.
// Weight columns are read from L2 exactly once per step per element.
// ---------------------------------------------------------------------------
__global__ __launch_bounds__(256) void gates_step_kernel(
    const float* __restrict__ Wih_f, const float* __restrict__ Whh_f,
    const float* __restrict__ Wih_b, const float* __restrict__ Whh_b,
    const float* __restrict__ mask_p, float* __restrict__ out, int t)
{
    __shared__ float zs[64][65];   // padded to kill bank conflicts
    __shared__ float ws[64][16];   // [kk][idx*4 + gate]

    const int bid   = blockIdx.x;
    const int dir   = bid >> 6;
    const int slice = bid & 63;
    const int hbase = slice * 4;
    const int tid = threadIdx.x;
    const int b   = tid & 63;
    const int idx = tid >> 6;           // 0..3
    const int bufR = t & 1;
    const int bufW = bufR ^ 1;

    const float* Wih = dir ? Wih_b : Wih_f;
    const float* Whh = dir ? Whh_b : Whh_f;
    const float* ctx_base = g_ctx + dir * (B * DQ);
    const float* h_base   = g_h + bufR * (2 * B * NH) + dir * (B * NH);

    float ai = 0.f, af = 0.f, ag = 0.f, ao = 0.f;

    for (int kc = 0; kc < DQ + NH; kc += 64) {
        // load z chunk [64 b][64 k]
        const float* src;
        int ld;
        if (kc < DQ) { src = ctx_base + kc; ld = DQ; }
        else         { src = h_base + (kc - DQ); ld = NH; }
#pragma unroll
        for (int i = tid; i < 64 * 64; i += 256) {
            int bb = i >> 6, kk = i & 63;
            zs[bb][kk] = src[bb * ld + kk];
        }
        // load weight chunk [64 k][16 cols]
        const float* wsrc = (kc < DQ) ? (Wih + (size_t)(DQ + kc) * G4)
                                      : (Whh + (size_t)(kc - DQ) * G4);
#pragma unroll
        for (int i = tid; i < 64 * 16; i += 256) {
            int kk = i >> 4, c = i & 15;
            int col = (c & 3) * NH + hbase + (c >> 2);
            ws[kk][c] = wsrc[(size_t)kk * G4 + col];
        }
        __syncthreads();

#pragma unroll
        for (int kk = 0; kk < 64; kk++) {
            float a = zs[b][kk];
            float4 w = *(const float4*)&ws[kk][idx * 4];
            ai = fmaf(a, w.x, ai);
            af = fmaf(a, w.y, af);
            ag = fmaf(a, w.z, ag);
            ao = fmaf(a, w.w, ao);
        }
        __syncthreads();
    }

    // LSTM update
    const int tsel = dir ? (TP - 1 - t) : t;
    const int hcol = hbase + idx;
    const float* Pih = (dir ? g_PihB : g_PihF) + ((size_t)b * TP + tsel) * G4;

    float gi = ai + Pih[hcol];
    float gf = af + Pih[NH + hcol];
    float gg = ag + Pih[2 * NH + hcol];
    float go = ao + Pih[3 * NH + hcol];

    float i_ = fsigmoid(gi);
    float f_ = fsigmoid(gf);
    float o_ = fsigmoid(go);
    float g_ = ftanh(gg);

    int sidx = dir * (B * NH) + b * NH + hcol;
    float c_old = g_c[sidx];
    float h_old = g_h[bufR * (2 * B * NH) + sidx];
    float nc = f_ * c_old + i_ * g_;
    float nh = o_ * ftanh(nc);

    float m = mask_p[b * TP + tsel];
    float hn = m * nh + (1.f - m) * h_old;
    float cn = m * nc + (1.f - m) * c_old;

    g_h[bufW * (2 * B * NH) + sidx] = hn;
    g_c[sidx] = cn;
    out[((size_t)b * TP + tsel) * (2 * NH) + dir * NH + hcol] = hn * m;
}

// ---------------------------------------------------------------------------
// Epilogue: concat_last = [h_f_final, h_b_final] (buffer (TP&1)==0)
// ---------------------------------------------------------------------------
__global__ void finalize_kernel(float* __restrict__ out) {
    int i = blockIdx.x * 256 + threadIdx.x;   // 2*B*NH = 32768
    int dir = i / (B * NH);
    int b   = (i / NH) & 63;
    int h   = i & (NH - 1);
    const size_t OFF_LAST = (size_t)B * TP * (2 * NH);
    out[OFF_LAST + b * (2 * NH) + dir * NH + h] =
        g_h[/*buf0*/ dir * (B * NH) + b * NH + h];
}

// ---------------------------------------------------------------------------
// Launch
// ---------------------------------------------------------------------------
extern "C" void kernel_launch(void* const* d_in, const int* in_sizes, int n_in,
                              void* d_out, int out_size)
{
    const float* input_p = (const float*)d_in[0];
    const float* mask_p  = (const float*)d_in[1];
    const float* input_q = (const float*)d_in[2];
    const float* mask_q  = (const float*)d_in[3];
    const float* Wp      = (const float*)d_in[4];
    const float* Wq      = (const float*)d_in[5];
    const float* Wr      = (const float*)d_in[6];
    const float* b_att   = (const float*)d_in[7];
    const float* w_score = (const float*)d_in[8];
    const float* Wih_f   = (const float*)d_in[9];
    const float* Whh_f   = (const float*)d_in[10];
    const float* b_f     = (const float*)d_in[11];
    const float* Wih_b   = (const float*)d_in[12];
    const float* Whh_b   = (const float*)d_in[13];
    const float* b_b     = (const float*)d_in[14];
    float* out = (float*)d_out;

    float *pproj, *qwq, *pihf, *pihb;
    cudaGetSymbolAddress((void**)&pproj, g_Pproj);
    cudaGetSymbolAddress((void**)&qwq,   g_qWq);
    cudaGetSymbolAddress((void**)&pihf,  g_PihF);
    cudaGetSymbolAddress((void**)&pihb,  g_PihB);

    // reset states (required: kernel is replayed)
    init_states<<<128, 256>>>();

    // time-parallel precompute GEMMs
    sgemm128<<<dim3(2, 30), 256>>>(input_q, Wq, b_att, qwq, B * TQ, NH, DQ, NH);
    sgemm128<<<dim3(2, 200), 256>>>(input_p, Wp, nullptr, pproj, B * TP, NH, DP, NH);
    sgemm128<<<dim3(8, 200), 256>>>(input_p, Wih_f, b_f, pihf, B * TP, G4, DP, G4);
    sgemm128<<<dim3(8, 200), 256>>>(input_p, Wih_b, b_b, pihb, B * TP, G4, DP, G4);

    // sequential recurrence (fwd + bwd run concurrently inside each kernel)
    for (int t = 0; t < TP; t++) {
        attn_step_kernel<<<128, 256>>>(input_q, mask_q, Wr, w_score, t);
        gates_step_kernel<<<128, 256>>>(Wih_f, Whh_f, Wih_b, Whh_b,
                                        mask_p, out, t);
    }

    finalize_kernel<<<128, 256>>>(out);
}